// round 2
// baseline (speedup 1.0000x reference)
#include <cuda_runtime.h>
#include <math.h>

#define B_   4
#define L_   2048
#define H_   2048
#define NH_  16
#define HD_  128
#define M_   8192           // B*L
#define N1_  6144           // 3*H

// ---------------- scratch (device globals; no runtime allocation) ----------
__device__ float g_qkv[(size_t)M_ * N1_];                 // raw qkv = x@Wqkv + b
__device__ float g_q[(size_t)B_ * NH_ * L_ * HD_];        // [b,h,l,d], pre-scaled
__device__ float g_k[(size_t)B_ * NH_ * L_ * HD_];
__device__ float g_v[(size_t)B_ * NH_ * L_ * HD_];
__device__ float g_y[(size_t)M_ * H_];                    // attn out, [m][h*128+d]

// ---------------- generic 128x128x8 fp32 GEMM, C = A@B + bias (opt silu) ---
template<int SILU>
__global__ __launch_bounds__(256) void sgemm_kernel(
    const float* __restrict__ A, const float* __restrict__ Bm,
    const float* __restrict__ bias, float* __restrict__ C,
    int M, int N, int K)
{
    __shared__ float As[8 * 128];   // [k][m] (transposed)
    __shared__ float Bs[8 * 128];   // [k][n]

    const int m0 = blockIdx.y * 128;
    const int n0 = blockIdx.x * 128;
    const int tid = threadIdx.x;
    const int tx = tid & 15;
    const int ty = tid >> 4;

    const int a_row = tid >> 1;            // 0..127
    const int a_col = (tid & 1) << 2;      // 0 or 4
    const int b_row = tid >> 5;            // 0..7
    const int b_col = (tid & 31) << 2;     // 0..124

    const float* Ap = A + (size_t)(m0 + a_row) * K + a_col;
    const float* Bp = Bm + (size_t)b_row * N + n0 + b_col;

    float acc[8][8];
#pragma unroll
    for (int i = 0; i < 8; i++)
#pragma unroll
        for (int j = 0; j < 8; j++) acc[i][j] = 0.f;

    for (int kt = 0; kt < K; kt += 8) {
        float4 av = *(const float4*)(Ap + kt);
        As[(a_col + 0) * 128 + a_row] = av.x;
        As[(a_col + 1) * 128 + a_row] = av.y;
        As[(a_col + 2) * 128 + a_row] = av.z;
        As[(a_col + 3) * 128 + a_row] = av.w;
        *(float4*)&Bs[b_row * 128 + b_col] = *(const float4*)(Bp + (size_t)kt * N);
        __syncthreads();

#pragma unroll
        for (int k = 0; k < 8; k++) {
            float am[8], bn[8];
            *(float4*)&am[0] = *(float4*)&As[k * 128 + ty * 8];
            *(float4*)&am[4] = *(float4*)&As[k * 128 + ty * 8 + 4];
            *(float4*)&bn[0] = *(float4*)&Bs[k * 128 + tx * 8];
            *(float4*)&bn[4] = *(float4*)&Bs[k * 128 + tx * 8 + 4];
#pragma unroll
            for (int i = 0; i < 8; i++)
#pragma unroll
                for (int j = 0; j < 8; j++)
                    acc[i][j] = fmaf(am[i], bn[j], acc[i][j]);
        }
        __syncthreads();
    }

    float bv[8];
#pragma unroll
    for (int j = 0; j < 8; j++) bv[j] = bias[n0 + tx * 8 + j];

#pragma unroll
    for (int i = 0; i < 8; i++) {
        const size_t row = (size_t)(m0 + ty * 8 + i);
        float out[8];
#pragma unroll
        for (int j = 0; j < 8; j++) {
            float z = acc[i][j] + bv[j];
            out[j] = SILU ? (z / (1.f + expf(-z))) : z;
        }
        *(float4*)&C[row * N + n0 + tx * 8]     = *(float4*)&out[0];
        *(float4*)&C[row * N + n0 + tx * 8 + 4] = *(float4*)&out[4];
    }
}

// ---------------- RoPE + head-scatter ---------------------------------------
// q[b,h,l,d] = rot(q_raw)[b,l, d*16+h] * 1/sqrt(128); k likewise (no scale);
// v[b,h,l,d] = v_raw[b,l, d*16+h].
__global__ __launch_bounds__(256) void rope_scatter(
    const float* __restrict__ cosb, const float* __restrict__ sinb,
    const float* __restrict__ qkv,
    float* __restrict__ Qo, float* __restrict__ Ko, float* __restrict__ Vo)
{
    __shared__ float row[6144];
    __shared__ float cr[1024];
    __shared__ float sr[1024];

    const int m = blockIdx.x;          // 0..8191
    const int b = m >> 11;
    const int l = m & 2047;
    const float* src = qkv + (size_t)m * 6144;

    for (int i = threadIdx.x; i < 1536; i += 256)
        *(float4*)&row[i * 4] = *(const float4*)&src[i * 4];
    {
        int i4 = threadIdx.x;          // 256 float4 = 1024 floats
        *(float4*)&cr[i4 * 4] = *(const float4*)&cosb[(size_t)l * 1024 + i4 * 4];
        *(float4*)&sr[i4 * 4] = *(const float4*)&sinb[(size_t)l * 1024 + i4 * 4];
    }
    __syncthreads();

    const float scale = 0.08838834764831845f;   // 1/sqrt(128)
#pragma unroll
    for (int it = 0; it < 4; it++) {
        int u = it * 256 + threadIdx.x;     // 0..1023
        int h = u >> 6;                     // 0..15
        int dlo = u & 63;                   // 0..63
        int jj = dlo * 16 + h;              // 0..1023
        float c = cr[jj], s = sr[jj];
        float q1 = row[jj],        q2 = row[jj + 1024];
        float k1 = row[2048 + jj], k2 = row[3072 + jj];
        size_t base = (((size_t)b * 16 + h) * 2048 + l) * 128;
        Qo[base + dlo]      = ( q1 * c + q2 * s) * scale;
        Qo[base + dlo + 64] = (-q1 * s + q2 * c) * scale;
        Ko[base + dlo]      =  k1 * c + k2 * s;
        Ko[base + dlo + 64] = -k1 * s + k2 * c;
        Vo[base + dlo]      = row[4096 + jj];
        Vo[base + dlo + 64] = row[4096 + jj + 1024];
    }
}

// ---------------- causal flash attention (fp32, 64x64 tiles) ----------------
#define ASMEM_FLOATS (2 * 128 * 68 + 64 * 128 + 64 * 68)
#define ASMEM_BYTES  (ASMEM_FLOATS * 4)

__global__ __launch_bounds__(256) void attn_kernel(
    const float* __restrict__ Q, const float* __restrict__ Kg,
    const float* __restrict__ Vg, float* __restrict__ Y)
{
    extern __shared__ float smf[];
    float* Qst = smf;                  // [128][68]  (d-major, padded)
    float* Kst = Qst + 128 * 68;       // [128][68]
    float* Vs  = Kst + 128 * 68;       // [64][128]  row-major
    float* Ps  = Vs + 64 * 128;        // [64][68]

    const int tid = threadIdx.x;
    const int tx = tid & 15;
    const int ty = tid >> 4;
    const int qt = blockIdx.x;
    const int bh = blockIdx.y;
    const int b = bh >> 4, h = bh & 15;
    const int q0 = qt * 64;

    const float* Qb = Q  + (size_t)bh * L_ * HD_;
    const float* Kb = Kg + (size_t)bh * L_ * HD_;
    const float* Vb = Vg + (size_t)bh * L_ * HD_;

    for (int idx = tid; idx < 64 * 128; idx += 256) {
        int i = idx >> 7, d = idx & 127;
        Qst[d * 68 + i] = Qb[(size_t)(q0 + i) * 128 + d];
    }

    float m_r[4], l_r[4], acc[4][8];
#pragma unroll
    for (int r = 0; r < 4; r++) {
        m_r[r] = -1e30f; l_r[r] = 0.f;
#pragma unroll
        for (int c = 0; c < 8; c++) acc[r][c] = 0.f;
    }

    for (int kt = 0; kt <= qt; kt++) {
        const int k0 = kt * 64;
        __syncthreads();   // prior iter's PV done before we overwrite tiles
        for (int idx = tid; idx < 64 * 128; idx += 256) {
            int i = idx >> 7, d = idx & 127;
            float kv = Kb[(size_t)(k0 + i) * 128 + d];
            Kst[d * 68 + i] = kv;
            Vs[idx] = Vb[(size_t)(k0 + i) * 128 + d];
        }
        __syncthreads();

        // S = Q K^T  (4x4 per thread)
        float s[4][4];
#pragma unroll
        for (int r = 0; r < 4; r++)
#pragma unroll
            for (int c = 0; c < 4; c++) s[r][c] = 0.f;

#pragma unroll 4
        for (int d = 0; d < 128; d++) {
            float4 qv = *(float4*)&Qst[d * 68 + ty * 4];
            float4 kv = *(float4*)&Kst[d * 68 + tx * 4];
            float qa[4] = {qv.x, qv.y, qv.z, qv.w};
            float ka[4] = {kv.x, kv.y, kv.z, kv.w};
#pragma unroll
            for (int r = 0; r < 4; r++)
#pragma unroll
                for (int c = 0; c < 4; c++)
                    s[r][c] = fmaf(qa[r], ka[c], s[r][c]);
        }

        if (kt == qt) {
#pragma unroll
            for (int r = 0; r < 4; r++)
#pragma unroll
                for (int c = 0; c < 4; c++)
                    if (k0 + tx * 4 + c > q0 + ty * 4 + r) s[r][c] = -1e30f;
        }

        // online softmax; row-group = 16 consecutive lanes (tx)
#pragma unroll
        for (int r = 0; r < 4; r++) {
            float mx = fmaxf(fmaxf(s[r][0], s[r][1]), fmaxf(s[r][2], s[r][3]));
#pragma unroll
            for (int off = 8; off; off >>= 1)
                mx = fmaxf(mx, __shfl_xor_sync(0xffffffffu, mx, off));
            float mnew = fmaxf(m_r[r], mx);
            float p[4];
            float rs = 0.f;
#pragma unroll
            for (int c = 0; c < 4; c++) { p[c] = __expf(s[r][c] - mnew); rs += p[c]; }
#pragma unroll
            for (int off = 8; off; off >>= 1)
                rs += __shfl_xor_sync(0xffffffffu, rs, off);
            float f = __expf(m_r[r] - mnew);
            l_r[r] = l_r[r] * f + rs;
            m_r[r] = mnew;
#pragma unroll
            for (int c = 0; c < 8; c++) acc[r][c] *= f;
            *(float4*)&Ps[(ty * 4 + r) * 68 + tx * 4] = *(float4*)&p[0];
        }
        __syncthreads();

        // O += P V  (4 rows x 8 cols per thread)
#pragma unroll 2
        for (int j = 0; j < 64; j++) {
            float4 v0 = *(float4*)&Vs[j * 128 + tx * 8];
            float4 v1 = *(float4*)&Vs[j * 128 + tx * 8 + 4];
#pragma unroll
            for (int r = 0; r < 4; r++) {
                float p = Ps[(ty * 4 + r) * 68 + j];
                acc[r][0] = fmaf(p, v0.x, acc[r][0]);
                acc[r][1] = fmaf(p, v0.y, acc[r][1]);
                acc[r][2] = fmaf(p, v0.z, acc[r][2]);
                acc[r][3] = fmaf(p, v0.w, acc[r][3]);
                acc[r][4] = fmaf(p, v1.x, acc[r][4]);
                acc[r][5] = fmaf(p, v1.y, acc[r][5]);
                acc[r][6] = fmaf(p, v1.z, acc[r][6]);
                acc[r][7] = fmaf(p, v1.w, acc[r][7]);
            }
        }
    }

    // write Y[b, l, h*128 + d]  (coalesced)
#pragma unroll
    for (int r = 0; r < 4; r++) {
        const int qi = q0 + ty * 4 + r;
        const float inv = 1.f / l_r[r];
        float o[8];
#pragma unroll
        for (int c = 0; c < 8; c++) o[c] = acc[r][c] * inv;
        size_t base = ((size_t)(b * L_ + qi)) * H_ + h * HD_ + tx * 8;
        *(float4*)&Y[base]     = *(float4*)&o[0];
        *(float4*)&Y[base + 4] = *(float4*)&o[4];
    }
}

// ---------------- launch -----------------------------------------------------
extern "C" void kernel_launch(void* const* d_in, const int* in_sizes, int n_in,
                              void* d_out, int out_size)
{
    (void)in_sizes; (void)n_in; (void)out_size;
    const float* x    = (const float*)d_in[0];
    const float* Wqkv = (const float*)d_in[1];
    const float* bqkv = (const float*)d_in[2];
    const float* Wfc2 = (const float*)d_in[3];
    const float* bfc2 = (const float*)d_in[4];
    const float* cosb = (const float*)d_in[5];
    const float* sinb = (const float*)d_in[6];
    float* out = (float*)d_out;

    float *qkv_p, *q_p, *k_p, *v_p, *y_p;
    cudaGetSymbolAddress((void**)&qkv_p, g_qkv);
    cudaGetSymbolAddress((void**)&q_p, g_q);
    cudaGetSymbolAddress((void**)&k_p, g_k);
    cudaGetSymbolAddress((void**)&v_p, g_v);
    cudaGetSymbolAddress((void**)&y_p, g_y);

    cudaFuncSetAttribute(attn_kernel,
                         cudaFuncAttributeMaxDynamicSharedMemorySize, ASMEM_BYTES);

    // 1) qkv = x @ Wqkv + bqkv           [8192 x 6144]
    sgemm_kernel<0><<<dim3(48, 64), 256>>>(x, Wqkv, bqkv, qkv_p, M_, N1_, H_);
    // 2) RoPE + scatter into [b,h,l,d] (q pre-scaled by 1/sqrt(HD))
    rope_scatter<<<M_, 256>>>(cosb, sinb, qkv_p, q_p, k_p, v_p);
    // 3) causal flash attention -> y [m][h*128+d]
    attn_kernel<<<dim3(32, 64), 256, ASMEM_BYTES>>>(q_p, k_p, v_p, y_p);
    // 4) out = silu(y @ Wfc2 + bfc2)     [8192 x 2048]
    sgemm_kernel<1><<<dim3(16, 64), 256>>>(y_p, Wfc2, bfc2, out, M_, H_, H_);
}

// round 4
// speedup vs baseline: 1.6239x; 1.6239x over previous
#include <cuda_runtime.h>
#include <cuda_fp16.h>
#include <math.h>
#include <stdint.h>

#define B_   4
#define L_   2048
#define H_   2048
#define NH_  16
#define HD_  128
#define M_   8192           // B*L
#define N1_  6144           // 3*H

// ================= scratch ===================================================
__device__ float g_qkv[(size_t)M_ * N1_];
__device__ float g_q[(size_t)M_ * H_];
__device__ float g_k[(size_t)M_ * H_];
__device__ float g_v[(size_t)M_ * H_];
__device__ float g_y[(size_t)M_ * H_];
__device__ __half g_xh[(size_t)M_ * H_];
__device__ __half g_xl[(size_t)M_ * H_];
__device__ __half g_wq_h[(size_t)N1_ * H_];   // Wqkv^T [6144][2048]
__device__ __half g_wq_l[(size_t)N1_ * H_];
__device__ __half g_wf_h[(size_t)H_ * H_];    // Wfc2^T [2048][2048]
__device__ __half g_wf_l[(size_t)H_ * H_];
__device__ __half g_yh[(size_t)M_ * H_];
__device__ __half g_yl[(size_t)M_ * H_];

// ================= small helpers ============================================
__device__ __forceinline__ uint32_t smem_u32(const void* p) {
    uint32_t a;
    asm("{ .reg .u64 t; cvta.to.shared.u64 t, %1; cvt.u32.u64 %0, t; }"
        : "=r"(a) : "l"(p));
    return a;
}
__device__ __forceinline__ void ldsm4(uint32_t* r, uint32_t addr) {
    asm volatile("ldmatrix.sync.aligned.m8n8.x4.shared.b16 {%0,%1,%2,%3}, [%4];"
        : "=r"(r[0]), "=r"(r[1]), "=r"(r[2]), "=r"(r[3]) : "r"(addr));
}
__device__ __forceinline__ void mma16816(float* c, const uint32_t* a, const uint32_t* b) {
    asm volatile("mma.sync.aligned.m16n8k16.row.col.f32.f16.f16.f32 "
        "{%0,%1,%2,%3}, {%4,%5,%6,%7}, {%8,%9}, {%0,%1,%2,%3};"
        : "+f"(c[0]), "+f"(c[1]), "+f"(c[2]), "+f"(c[3])
        : "r"(a[0]), "r"(a[1]), "r"(a[2]), "r"(a[3]), "r"(b[0]), "r"(b[1]));
}
__device__ __forceinline__ void cp_async16(uint32_t saddr, const void* gaddr) {
    asm volatile("cp.async.cg.shared.global [%0], [%1], 16;"
                 :: "r"(saddr), "l"(gaddr));
}
#define CP_COMMIT() asm volatile("cp.async.commit_group;")
#define CP_WAIT(N)  asm volatile("cp.async.wait_group %0;" :: "n"(N))

// ================= conversion kernels =======================================
__global__ __launch_bounds__(256) void split_fp16(
    const float* __restrict__ X, __half* __restrict__ Xh, __half* __restrict__ Xl, int n4)
{
    int i = blockIdx.x * 256 + threadIdx.x;
    if (i >= n4) return;
    float4 v = *(const float4*)(X + (size_t)i * 4);
    float a[4] = {v.x, v.y, v.z, v.w};
    __half h[4], l[4];
#pragma unroll
    for (int j = 0; j < 4; j++) {
        h[j] = __float2half_rn(a[j]);
        l[j] = __float2half_rn(a[j] - __half2float(h[j]));
    }
    *(uint2*)(Xh + (size_t)i * 4) = *(uint2*)h;
    *(uint2*)(Xl + (size_t)i * 4) = *(uint2*)l;
}

// W [K x N] fp32 -> Wt hi/lo [N x K] fp16
__global__ __launch_bounds__(256) void transpose_split(
    const float* __restrict__ W, __half* __restrict__ Th, __half* __restrict__ Tl,
    int K, int N)
{
    __shared__ float t[32][33];
    int n0 = blockIdx.x * 32, k0 = blockIdx.y * 32;
    int tx = threadIdx.x, ty = threadIdx.y;
#pragma unroll
    for (int i = ty; i < 32; i += 8)
        t[i][tx] = W[(size_t)(k0 + i) * N + n0 + tx];
    __syncthreads();
#pragma unroll
    for (int i = ty; i < 32; i += 8) {
        float v = t[tx][i];
        __half h = __float2half_rn(v);
        Th[(size_t)(n0 + i) * K + k0 + tx] = h;
        Tl[(size_t)(n0 + i) * K + k0 + tx] = __float2half_rn(v - __half2float(h));
    }
}

// ================= split-fp16 warp-MMA GEMM =================================
// C[M x N] = (Ah+Al)[M x K] @ ((Bh+Bl)[N x K])^T + bias, fp32 out, opt silu.
// Block tile 128x128, K-step 32, 8 warps (warp tile 64x32), cp.async 2-stage.
// smem tile layout: rows of 32 halves padded to 40 (80B stride, ldsm-conflict-free)
#define GT_ROWSTRIDE 80                      // bytes per padded row
#define GT_TILE_B    (128 * GT_ROWSTRIDE)    // 10240 B per tile
#define GT_STAGE_B   (4 * GT_TILE_B)         // Ah, Al, Bh, Bl
#define GEMM_SMEM    (2 * GT_STAGE_B)        // 81920 B

template<int SILU>
__global__ __launch_bounds__(256, 1) void gemm_mma(
    const __half* __restrict__ Ah, const __half* __restrict__ Al,
    const __half* __restrict__ Bh, const __half* __restrict__ Bl,
    const float* __restrict__ bias, float* __restrict__ C,
    int Ng, int Kg)
{
    extern __shared__ char smem[];
    const uint32_t sb = smem_u32(smem);
    const int tid  = threadIdx.x;
    const int lane = tid & 31;
    const int wid  = tid >> 5;
    const int wm   = wid & 1;          // 2 warps in M
    const int wn   = wid >> 1;         // 4 warps in N
    const int m0 = blockIdx.y * 128;
    const int n0 = blockIdx.x * 128;

    const __half* gsrc[4] = { Ah + (size_t)m0 * Kg, Al + (size_t)m0 * Kg,
                              Bh + (size_t)n0 * Kg, Bl + (size_t)n0 * Kg };

    // ldmatrix lane addressing
    const int a_row = ((lane >> 3) & 1) * 8 + (lane & 7);
    const int a_kof = (lane >> 4) * 8;
    const int b_row = (lane >> 4) * 8 + (lane & 7);
    const int b_kof = ((lane >> 3) & 1) * 8;

    float acc[4][4][4];
#pragma unroll
    for (int i = 0; i < 4; i++)
#pragma unroll
        for (int j = 0; j < 4; j++)
#pragma unroll
            for (int k = 0; k < 4; k++) acc[i][j][k] = 0.f;

    const int nst = Kg >> 5;   // K/32 stages

    // ---- async load of one stage: 4 tiles x 512 16B-chunks, 8 per thread ----
    auto load_stage = [&](int s) {
        const uint32_t stb = sb + (s & 1) * GT_STAGE_B;
        const int k0 = s << 5;
#pragma unroll
        for (int j = 0; j < 8; j++) {
            int c = tid + j * 256;          // 0..2047
            int tile = c >> 9;              // 0..3
            int idx = c & 511;
            int r = idx >> 2, q = idx & 3;  // row, 16B chunk in row
            uint32_t sa = stb + tile * GT_TILE_B + r * GT_ROWSTRIDE + q * 16;
            cp_async16(sa, gsrc[tile] + (size_t)r * Kg + k0 + q * 8);
        }
        CP_COMMIT();
    };

    load_stage(0);

    for (int i = 0; i < nst; i++) {
        if (i + 1 < nst) { load_stage(i + 1); CP_WAIT(1); }
        else            { CP_WAIT(0); }
        __syncthreads();

        const uint32_t stb = sb + (i & 1) * GT_STAGE_B;
        const uint32_t sAh = stb;
        const uint32_t sAl = stb + GT_TILE_B;
        const uint32_t sBh = stb + 2 * GT_TILE_B;
        const uint32_t sBl = stb + 3 * GT_TILE_B;

#pragma unroll
        for (int kk = 0; kk < 2; kk++) {
            const int kb = kk * 16;
            uint32_t ah[4][4], al[4][4], bh[2][4], bl[2][4];
#pragma unroll
            for (int mi = 0; mi < 4; mi++) {
                uint32_t ro = (uint32_t)((wm * 64 + mi * 16 + a_row) * GT_ROWSTRIDE
                                         + (kb + a_kof) * 2);
                ldsm4(ah[mi], sAh + ro);
                ldsm4(al[mi], sAl + ro);
            }
#pragma unroll
            for (int nj = 0; nj < 2; nj++) {
                uint32_t ro = (uint32_t)((wn * 32 + nj * 16 + b_row) * GT_ROWSTRIDE
                                         + (kb + b_kof) * 2);
                ldsm4(bh[nj], sBh + ro);
                ldsm4(bl[nj], sBl + ro);
            }
#pragma unroll
            for (int mi = 0; mi < 4; mi++)
#pragma unroll
                for (int ni = 0; ni < 4; ni++) {
                    const uint32_t* bhf = &bh[ni >> 1][2 * (ni & 1)];
                    const uint32_t* blf = &bl[ni >> 1][2 * (ni & 1)];
                    mma16816(acc[mi][ni], ah[mi], bhf);   // hi*hi
                    mma16816(acc[mi][ni], ah[mi], blf);   // hi*lo
                    mma16816(acc[mi][ni], al[mi], bhf);   // lo*hi
                }
        }
        __syncthreads();
    }

    // ---- epilogue ----
    const int g = lane >> 2, t4 = lane & 3;
#pragma unroll
    for (int mi = 0; mi < 4; mi++) {
#pragma unroll
        for (int ni = 0; ni < 4; ni++) {
            int row0 = m0 + wm * 64 + mi * 16 + g;
            int col  = n0 + wn * 32 + ni * 8 + t4 * 2;
            float b0 = bias[col], b1 = bias[col + 1];
            float z0 = acc[mi][ni][0] + b0, z1 = acc[mi][ni][1] + b1;
            float z2 = acc[mi][ni][2] + b0, z3 = acc[mi][ni][3] + b1;
            if (SILU) {
                z0 = z0 / (1.f + expf(-z0)); z1 = z1 / (1.f + expf(-z1));
                z2 = z2 / (1.f + expf(-z2)); z3 = z3 / (1.f + expf(-z3));
            }
            *(float2*)&C[(size_t)row0 * Ng + col]       = make_float2(z0, z1);
            *(float2*)&C[(size_t)(row0 + 8) * Ng + col] = make_float2(z2, z3);
        }
    }
}

// ================= RoPE + head-scatter (fp32) ===============================
__global__ __launch_bounds__(256) void rope_scatter(
    const float* __restrict__ cosb, const float* __restrict__ sinb,
    const float* __restrict__ qkv,
    float* __restrict__ Qo, float* __restrict__ Ko, float* __restrict__ Vo)
{
    __shared__ float row[6144];
    __shared__ float cr[1024];
    __shared__ float sr[1024];

    const int m = blockIdx.x;
    const int b = m >> 11;
    const int l = m & 2047;
    const float* src = qkv + (size_t)m * 6144;

    for (int i = threadIdx.x; i < 1536; i += 256)
        *(float4*)&row[i * 4] = *(const float4*)&src[i * 4];
    {
        int i4 = threadIdx.x;
        *(float4*)&cr[i4 * 4] = *(const float4*)&cosb[(size_t)l * 1024 + i4 * 4];
        *(float4*)&sr[i4 * 4] = *(const float4*)&sinb[(size_t)l * 1024 + i4 * 4];
    }
    __syncthreads();

    const float scale = 0.08838834764831845f;
#pragma unroll
    for (int it = 0; it < 4; it++) {
        int u = it * 256 + threadIdx.x;
        int h = u >> 6;
        int dlo = u & 63;
        int jj = dlo * 16 + h;
        float c = cr[jj], s = sr[jj];
        float q1 = row[jj],        q2 = row[jj + 1024];
        float k1 = row[2048 + jj], k2 = row[3072 + jj];
        size_t base = (((size_t)b * 16 + h) * 2048 + l) * 128;
        Qo[base + dlo]      = ( q1 * c + q2 * s) * scale;
        Qo[base + dlo + 64] = (-q1 * s + q2 * c) * scale;
        Ko[base + dlo]      =  k1 * c + k2 * s;
        Ko[base + dlo + 64] = -k1 * s + k2 * c;
        Vo[base + dlo]      = row[4096 + jj];
        Vo[base + dlo + 64] = row[4096 + jj + 1024];
    }
}

// ================= causal flash attention (fp32) ============================
#define ASMEM_FLOATS (2 * 128 * 68 + 64 * 128 + 64 * 68)
#define ASMEM_BYTES  (ASMEM_FLOATS * 4)

__global__ __launch_bounds__(256) void attn_kernel(
    const float* __restrict__ Q, const float* __restrict__ Kg,
    const float* __restrict__ Vg, float* __restrict__ Y)
{
    extern __shared__ float smf[];
    float* Qst = smf;
    float* Kst = Qst + 128 * 68;
    float* Vs  = Kst + 128 * 68;
    float* Ps  = Vs + 64 * 128;

    const int tid = threadIdx.x;
    const int tx = tid & 15;
    const int ty = tid >> 4;
    const int qt = blockIdx.x;
    const int bh = blockIdx.y;
    const int b = bh >> 4, h = bh & 15;
    const int q0 = qt * 64;

    const float* Qb = Q  + (size_t)bh * L_ * HD_;
    const float* Kb = Kg + (size_t)bh * L_ * HD_;
    const float* Vb = Vg + (size_t)bh * L_ * HD_;

    for (int idx = tid; idx < 64 * 128; idx += 256) {
        int i = idx >> 7, d = idx & 127;
        Qst[d * 68 + i] = Qb[(size_t)(q0 + i) * 128 + d];
    }

    float m_r[4], l_r[4], acc[4][8];
#pragma unroll
    for (int r = 0; r < 4; r++) {
        m_r[r] = -1e30f; l_r[r] = 0.f;
#pragma unroll
        for (int c = 0; c < 8; c++) acc[r][c] = 0.f;
    }

    for (int kt = 0; kt <= qt; kt++) {
        const int k0 = kt * 64;
        __syncthreads();
        for (int idx = tid; idx < 64 * 128; idx += 256) {
            int i = idx >> 7, d = idx & 127;
            float kv = Kb[(size_t)(k0 + i) * 128 + d];
            Kst[d * 68 + i] = kv;
            Vs[idx] = Vb[(size_t)(k0 + i) * 128 + d];
        }
        __syncthreads();

        float s[4][4];
#pragma unroll
        for (int r = 0; r < 4; r++)
#pragma unroll
            for (int c = 0; c < 4; c++) s[r][c] = 0.f;

#pragma unroll 4
        for (int d = 0; d < 128; d++) {
            float4 qv = *(float4*)&Qst[d * 68 + ty * 4];
            float4 kv = *(float4*)&Kst[d * 68 + tx * 4];
            float qa[4] = {qv.x, qv.y, qv.z, qv.w};
            float ka[4] = {kv.x, kv.y, kv.z, kv.w};
#pragma unroll
            for (int r = 0; r < 4; r++)
#pragma unroll
                for (int c = 0; c < 4; c++)
                    s[r][c] = fmaf(qa[r], ka[c], s[r][c]);
        }

        if (kt == qt) {
#pragma unroll
            for (int r = 0; r < 4; r++)
#pragma unroll
                for (int c = 0; c < 4; c++)
                    if (k0 + tx * 4 + c > q0 + ty * 4 + r) s[r][c] = -1e30f;
        }

#pragma unroll
        for (int r = 0; r < 4; r++) {
            float mx = fmaxf(fmaxf(s[r][0], s[r][1]), fmaxf(s[r][2], s[r][3]));
#pragma unroll
            for (int off = 8; off; off >>= 1)
                mx = fmaxf(mx, __shfl_xor_sync(0xffffffffu, mx, off));
            float mnew = fmaxf(m_r[r], mx);
            float p[4];
            float rs = 0.f;
#pragma unroll
            for (int c = 0; c < 4; c++) { p[c] = __expf(s[r][c] - mnew); rs += p[c]; }
#pragma unroll
            for (int off = 8; off; off >>= 1)
                rs += __shfl_xor_sync(0xffffffffu, rs, off);
            float f = __expf(m_r[r] - mnew);
            l_r[r] = l_r[r] * f + rs;
            m_r[r] = mnew;
#pragma unroll
            for (int c = 0; c < 8; c++) acc[r][c] *= f;
            *(float4*)&Ps[(ty * 4 + r) * 68 + tx * 4] = *(float4*)&p[0];
        }
        __syncthreads();

#pragma unroll 2
        for (int j = 0; j < 64; j++) {
            float4 v0 = *(float4*)&Vs[j * 128 + tx * 8];
            float4 v1 = *(float4*)&Vs[j * 128 + tx * 8 + 4];
#pragma unroll
            for (int r = 0; r < 4; r++) {
                float p = Ps[(ty * 4 + r) * 68 + j];
                acc[r][0] = fmaf(p, v0.x, acc[r][0]);
                acc[r][1] = fmaf(p, v0.y, acc[r][1]);
                acc[r][2] = fmaf(p, v0.z, acc[r][2]);
                acc[r][3] = fmaf(p, v0.w, acc[r][3]);
                acc[r][4] = fmaf(p, v1.x, acc[r][4]);
                acc[r][5] = fmaf(p, v1.y, acc[r][5]);
                acc[r][6] = fmaf(p, v1.z, acc[r][6]);
                acc[r][7] = fmaf(p, v1.w, acc[r][7]);
            }
        }
    }

#pragma unroll
    for (int r = 0; r < 4; r++) {
        const int qi = q0 + ty * 4 + r;
        const float inv = 1.f / l_r[r];
        float o[8];
#pragma unroll
        for (int c = 0; c < 8; c++) o[c] = acc[r][c] * inv;
        size_t base = ((size_t)(b * L_ + qi)) * H_ + h * HD_ + tx * 8;
        *(float4*)&Y[base]     = *(float4*)&o[0];
        *(float4*)&Y[base + 4] = *(float4*)&o[4];
    }
}

// ================= launch ====================================================
extern "C" void kernel_launch(void* const* d_in, const int* in_sizes, int n_in,
                              void* d_out, int out_size)
{
    (void)in_sizes; (void)n_in; (void)out_size;
    const float* x    = (const float*)d_in[0];
    const float* Wqkv = (const float*)d_in[1];
    const float* bqkv = (const float*)d_in[2];
    const float* Wfc2 = (const float*)d_in[3];
    const float* bfc2 = (const float*)d_in[4];
    const float* cosb = (const float*)d_in[5];
    const float* sinb = (const float*)d_in[6];
    float* out = (float*)d_out;

    float *qkv_p, *q_p, *k_p, *v_p, *y_p;
    __half *xh, *xl, *wqh, *wql, *wfh, *wfl, *yh, *yl;
    cudaGetSymbolAddress((void**)&qkv_p, g_qkv);
    cudaGetSymbolAddress((void**)&q_p, g_q);
    cudaGetSymbolAddress((void**)&k_p, g_k);
    cudaGetSymbolAddress((void**)&v_p, g_v);
    cudaGetSymbolAddress((void**)&y_p, g_y);
    cudaGetSymbolAddress((void**)&xh, g_xh);
    cudaGetSymbolAddress((void**)&xl, g_xl);
    cudaGetSymbolAddress((void**)&wqh, g_wq_h);
    cudaGetSymbolAddress((void**)&wql, g_wq_l);
    cudaGetSymbolAddress((void**)&wfh, g_wf_h);
    cudaGetSymbolAddress((void**)&wfl, g_wf_l);
    cudaGetSymbolAddress((void**)&yh, g_yh);
    cudaGetSymbolAddress((void**)&yl, g_yl);

    cudaFuncSetAttribute(attn_kernel,
                         cudaFuncAttributeMaxDynamicSharedMemorySize, ASMEM_BYTES);
    cudaFuncSetAttribute(gemm_mma<0>,
                         cudaFuncAttributeMaxDynamicSharedMemorySize, GEMM_SMEM);
    cudaFuncSetAttribute(gemm_mma<1>,
                         cudaFuncAttributeMaxDynamicSharedMemorySize, GEMM_SMEM);

    // input conversions
    split_fp16<<<(M_ * H_) / 1024, 256>>>(x, xh, xl, (M_ * H_) / 4);
    transpose_split<<<dim3(N1_ / 32, H_ / 32), dim3(32, 8)>>>(Wqkv, wqh, wql, H_, N1_);
    transpose_split<<<dim3(H_ / 32, H_ / 32), dim3(32, 8)>>>(Wfc2, wfh, wfl, H_, H_);

    // 1) qkv = x @ Wqkv + bqkv  (split-fp16 warp MMA)
    gemm_mma<0><<<dim3(N1_ / 128, M_ / 128), 256, GEMM_SMEM>>>(
        xh, xl, wqh, wql, bqkv, qkv_p, N1_, H_);
    // 2) RoPE + head scatter
    rope_scatter<<<M_, 256>>>(cosb, sinb, qkv_p, q_p, k_p, v_p);
    // 3) causal flash attention (fp32)
    attn_kernel<<<dim3(32, 64), 256, ASMEM_BYTES>>>(q_p, k_p, v_p, y_p);
    // 4) out = silu(y @ Wfc2 + bfc2)
    split_fp16<<<(M_ * H_) / 1024, 256>>>(y_p, yh, yl, (M_ * H_) / 4);
    gemm_mma<1><<<dim3(H_ / 128, M_ / 128), 256, GEMM_SMEM>>>(
        yh, yl, wfh, wfl, bfc2, out, H_, H_);
}

// round 7
// speedup vs baseline: 2.8956x; 1.7831x over previous
#include <cuda_runtime.h>
#include <cuda_fp16.h>
#include <math.h>
#include <stdint.h>

#define B_   4
#define L_   2048
#define H_   2048
#define NH_  16
#define HD_  128
#define M_   8192           // B*L
#define N1_  6144           // 3*H

// ================= scratch ===================================================
__device__ float g_qkv[(size_t)M_ * N1_];
__device__ __half g_xh[(size_t)M_ * H_];
__device__ __half g_xl[(size_t)M_ * H_];
__device__ __half g_wq_h[(size_t)N1_ * H_];   // Wqkv^T [6144][2048]
__device__ __half g_wq_l[(size_t)N1_ * H_];
__device__ __half g_wf_h[(size_t)H_ * H_];    // Wfc2^T [2048][2048]
__device__ __half g_wf_l[(size_t)H_ * H_];
__device__ __half g_yh[(size_t)M_ * H_];
__device__ __half g_yl[(size_t)M_ * H_];
__device__ __half g_qh[(size_t)M_ * H_];      // [b,h,l,d] fp16 hi/lo
__device__ __half g_ql[(size_t)M_ * H_];
__device__ __half g_kh[(size_t)M_ * H_];
__device__ __half g_kl[(size_t)M_ * H_];
__device__ __half g_vh[(size_t)M_ * H_];
__device__ __half g_vl[(size_t)M_ * H_];

// ================= small helpers ============================================
__device__ __forceinline__ uint32_t smem_u32(const void* p) {
    uint32_t a;
    asm("{ .reg .u64 t; cvta.to.shared.u64 t, %1; cvt.u32.u64 %0, t; }"
        : "=r"(a) : "l"(p));
    return a;
}
__device__ __forceinline__ void ldsm4(uint32_t* r, uint32_t addr) {
    asm volatile("ldmatrix.sync.aligned.m8n8.x4.shared.b16 {%0,%1,%2,%3}, [%4];"
        : "=r"(r[0]), "=r"(r[1]), "=r"(r[2]), "=r"(r[3]) : "r"(addr));
}
__device__ __forceinline__ void ldsm4t(uint32_t* r, uint32_t addr) {
    asm volatile("ldmatrix.sync.aligned.m8n8.x4.trans.shared.b16 {%0,%1,%2,%3}, [%4];"
        : "=r"(r[0]), "=r"(r[1]), "=r"(r[2]), "=r"(r[3]) : "r"(addr));
}
__device__ __forceinline__ void mma16816(float* c, const uint32_t* a, const uint32_t* b) {
    asm volatile("mma.sync.aligned.m16n8k16.row.col.f32.f16.f16.f32 "
        "{%0,%1,%2,%3}, {%4,%5,%6,%7}, {%8,%9}, {%0,%1,%2,%3};"
        : "+f"(c[0]), "+f"(c[1]), "+f"(c[2]), "+f"(c[3])
        : "r"(a[0]), "r"(a[1]), "r"(a[2]), "r"(a[3]), "r"(b[0]), "r"(b[1]));
}
__device__ __forceinline__ void cp_async16(uint32_t saddr, const void* gaddr) {
    asm volatile("cp.async.cg.shared.global [%0], [%1], 16;"
                 :: "r"(saddr), "l"(gaddr));
}
#define CP_COMMIT() asm volatile("cp.async.commit_group;")
#define CP_WAIT(N)  asm volatile("cp.async.wait_group %0;" :: "n"(N))

// ================= conversion kernels =======================================
__global__ __launch_bounds__(256) void split_fp16(
    const float* __restrict__ X, __half* __restrict__ Xh, __half* __restrict__ Xl, int n4)
{
    int i = blockIdx.x * 256 + threadIdx.x;
    if (i >= n4) return;
    float4 v = *(const float4*)(X + (size_t)i * 4);
    float a[4] = {v.x, v.y, v.z, v.w};
    __half h[4], l[4];
#pragma unroll
    for (int j = 0; j < 4; j++) {
        h[j] = __float2half_rn(a[j]);
        l[j] = __float2half_rn(a[j] - __half2float(h[j]));
    }
    *(uint2*)(Xh + (size_t)i * 4) = *(uint2*)h;
    *(uint2*)(Xl + (size_t)i * 4) = *(uint2*)l;
}

// W [K x N] fp32 -> Wt hi/lo [N x K] fp16
__global__ __launch_bounds__(256) void transpose_split(
    const float* __restrict__ W, __half* __restrict__ Th, __half* __restrict__ Tl,
    int K, int N)
{
    __shared__ float t[32][33];
    int n0 = blockIdx.x * 32, k0 = blockIdx.y * 32;
    int tx = threadIdx.x, ty = threadIdx.y;
#pragma unroll
    for (int i = ty; i < 32; i += 8)
        t[i][tx] = W[(size_t)(k0 + i) * N + n0 + tx];
    __syncthreads();
#pragma unroll
    for (int i = ty; i < 32; i += 8) {
        float v = t[tx][i];
        __half h = __float2half_rn(v);
        Th[(size_t)(n0 + i) * K + k0 + tx] = h;
        Tl[(size_t)(n0 + i) * K + k0 + tx] = __float2half_rn(v - __half2float(h));
    }
}

// ================= split-fp16 warp-MMA GEMM (unchanged from R4) =============
#define GT_ROWSTRIDE 80
#define GT_TILE_B    (128 * GT_ROWSTRIDE)
#define GT_STAGE_B   (4 * GT_TILE_B)
#define GEMM_SMEM    (2 * GT_STAGE_B)

template<int SILU>
__global__ __launch_bounds__(256, 1) void gemm_mma(
    const __half* __restrict__ Ah, const __half* __restrict__ Al,
    const __half* __restrict__ Bh, const __half* __restrict__ Bl,
    const float* __restrict__ bias, float* __restrict__ C,
    int Ng, int Kg)
{
    extern __shared__ char smem[];
    const uint32_t sb = smem_u32(smem);
    const int tid  = threadIdx.x;
    const int lane = tid & 31;
    const int wid  = tid >> 5;
    const int wm   = wid & 1;
    const int wn   = wid >> 1;
    const int m0 = blockIdx.y * 128;
    const int n0 = blockIdx.x * 128;

    const __half* gsrc[4] = { Ah + (size_t)m0 * Kg, Al + (size_t)m0 * Kg,
                              Bh + (size_t)n0 * Kg, Bl + (size_t)n0 * Kg };

    const int a_row = ((lane >> 3) & 1) * 8 + (lane & 7);
    const int a_kof = (lane >> 4) * 8;
    const int b_row = (lane >> 4) * 8 + (lane & 7);
    const int b_kof = ((lane >> 3) & 1) * 8;

    float acc[4][4][4];
#pragma unroll
    for (int i = 0; i < 4; i++)
#pragma unroll
        for (int j = 0; j < 4; j++)
#pragma unroll
            for (int k = 0; k < 4; k++) acc[i][j][k] = 0.f;

    const int nst = Kg >> 5;

    auto load_stage = [&](int s) {
        const uint32_t stb = sb + (s & 1) * GT_STAGE_B;
        const int k0 = s << 5;
#pragma unroll
        for (int j = 0; j < 8; j++) {
            int c = tid + j * 256;
            int tile = c >> 9;
            int idx = c & 511;
            int r = idx >> 2, q = idx & 3;
            uint32_t sa = stb + tile * GT_TILE_B + r * GT_ROWSTRIDE + q * 16;
            cp_async16(sa, gsrc[tile] + (size_t)r * Kg + k0 + q * 8);
        }
        CP_COMMIT();
    };

    load_stage(0);

    for (int i = 0; i < nst; i++) {
        if (i + 1 < nst) { load_stage(i + 1); CP_WAIT(1); }
        else            { CP_WAIT(0); }
        __syncthreads();

        const uint32_t stb = sb + (i & 1) * GT_STAGE_B;
        const uint32_t sAh = stb;
        const uint32_t sAl = stb + GT_TILE_B;
        const uint32_t sBh = stb + 2 * GT_TILE_B;
        const uint32_t sBl = stb + 3 * GT_TILE_B;

#pragma unroll
        for (int kk = 0; kk < 2; kk++) {
            const int kb = kk * 16;
            uint32_t ah[4][4], al[4][4], bh[2][4], bl[2][4];
#pragma unroll
            for (int mi = 0; mi < 4; mi++) {
                uint32_t ro = (uint32_t)((wm * 64 + mi * 16 + a_row) * GT_ROWSTRIDE
                                         + (kb + a_kof) * 2);
                ldsm4(ah[mi], sAh + ro);
                ldsm4(al[mi], sAl + ro);
            }
#pragma unroll
            for (int nj = 0; nj < 2; nj++) {
                uint32_t ro = (uint32_t)((wn * 32 + nj * 16 + b_row) * GT_ROWSTRIDE
                                         + (kb + b_kof) * 2);
                ldsm4(bh[nj], sBh + ro);
                ldsm4(bl[nj], sBl + ro);
            }
#pragma unroll
            for (int mi = 0; mi < 4; mi++)
#pragma unroll
                for (int ni = 0; ni < 4; ni++) {
                    const uint32_t* bhf = &bh[ni >> 1][2 * (ni & 1)];
                    const uint32_t* blf = &bl[ni >> 1][2 * (ni & 1)];
                    mma16816(acc[mi][ni], ah[mi], bhf);
                    mma16816(acc[mi][ni], ah[mi], blf);
                    mma16816(acc[mi][ni], al[mi], bhf);
                }
        }
        __syncthreads();
    }

    const int g = lane >> 2, t4 = lane & 3;
#pragma unroll
    for (int mi = 0; mi < 4; mi++) {
#pragma unroll
        for (int ni = 0; ni < 4; ni++) {
            int row0 = m0 + wm * 64 + mi * 16 + g;
            int col  = n0 + wn * 32 + ni * 8 + t4 * 2;
            float b0 = bias[col], b1 = bias[col + 1];
            float z0 = acc[mi][ni][0] + b0, z1 = acc[mi][ni][1] + b1;
            float z2 = acc[mi][ni][2] + b0, z3 = acc[mi][ni][3] + b1;
            if (SILU) {
                z0 = z0 / (1.f + expf(-z0)); z1 = z1 / (1.f + expf(-z1));
                z2 = z2 / (1.f + expf(-z2)); z3 = z3 / (1.f + expf(-z3));
            }
            *(float2*)&C[(size_t)row0 * Ng + col]       = make_float2(z0, z1);
            *(float2*)&C[(size_t)(row0 + 8) * Ng + col] = make_float2(z2, z3);
        }
    }
}

// ================= RoPE + head-scatter -> fp16 hi/lo ========================
__global__ __launch_bounds__(256) void rope_scatter(
    const float* __restrict__ cosb, const float* __restrict__ sinb,
    const float* __restrict__ qkv,
    __half* __restrict__ Qh, __half* __restrict__ Ql,
    __half* __restrict__ Kh, __half* __restrict__ Kl,
    __half* __restrict__ Vh, __half* __restrict__ Vl)
{
    __shared__ float row[6144];
    __shared__ float cr[1024];
    __shared__ float sr[1024];

    const int m = blockIdx.x;
    const int b = m >> 11;
    const int l = m & 2047;
    const float* src = qkv + (size_t)m * 6144;

    for (int i = threadIdx.x; i < 1536; i += 256)
        *(float4*)&row[i * 4] = *(const float4*)&src[i * 4];
    {
        int i4 = threadIdx.x;
        *(float4*)&cr[i4 * 4] = *(const float4*)&cosb[(size_t)l * 1024 + i4 * 4];
        *(float4*)&sr[i4 * 4] = *(const float4*)&sinb[(size_t)l * 1024 + i4 * 4];
    }
    __syncthreads();

    const float scale = 0.08838834764831845f;
#pragma unroll
    for (int it = 0; it < 4; it++) {
        int u = it * 256 + threadIdx.x;
        int h = u >> 6;
        int dlo = u & 63;
        int jj = dlo * 16 + h;
        float c = cr[jj], s = sr[jj];
        float q1 = row[jj],        q2 = row[jj + 1024];
        float k1 = row[2048 + jj], k2 = row[3072 + jj];
        size_t base = (((size_t)b * 16 + h) * 2048 + l) * 128;
        float vals[6];
        vals[0] = ( q1 * c + q2 * s) * scale;
        vals[1] = (-q1 * s + q2 * c) * scale;
        vals[2] =  k1 * c + k2 * s;
        vals[3] = -k1 * s + k2 * c;
        vals[4] = row[4096 + jj];
        vals[5] = row[4096 + jj + 1024];
        __half* dsth[3] = {Qh, Kh, Vh};
        __half* dstl[3] = {Ql, Kl, Vl};
#pragma unroll
        for (int p = 0; p < 3; p++) {
#pragma unroll
            for (int q = 0; q < 2; q++) {
                float v = vals[p * 2 + q];
                __half hh = __float2half_rn(v);
                dsth[p][base + dlo + q * 64] = hh;
                dstl[p][base + dlo + q * 64] = __float2half_rn(v - __half2float(hh));
            }
        }
    }
}

// ================= causal flash attention (split-fp16 HMMA) =================
// Block: 64 q-rows, 4 warps (warp = 16 q-rows). K/V tiles of 64 rows.
#define AT_SW 136                               // halves per padded row (272 B)
#define AT_TILE_H (64 * AT_SW)                  // halves per tile
#define ATT_SMEM (6 * AT_TILE_H * 2)            // 104448 B

__global__ __launch_bounds__(128) void attn_mma(
    const __half* __restrict__ Qhg, const __half* __restrict__ Qlg,
    const __half* __restrict__ Khg, const __half* __restrict__ Klg,
    const __half* __restrict__ Vhg, const __half* __restrict__ Vlg,
    __half* __restrict__ Yh, __half* __restrict__ Yl)
{
    extern __shared__ __half smh[];
    __half* sQh = smh;
    __half* sQl = sQh + AT_TILE_H;
    __half* sKh = sQl + AT_TILE_H;
    __half* sKl = sKh + AT_TILE_H;
    __half* sVh = sKl + AT_TILE_H;
    __half* sVl = sVh + AT_TILE_H;

    const uint32_t uQh = smem_u32(sQh), uQl = smem_u32(sQl);
    const uint32_t uKh = smem_u32(sKh), uKl = smem_u32(sKl);
    const uint32_t uVh = smem_u32(sVh), uVl = smem_u32(sVl);

    const int tid = threadIdx.x;
    const int lane = tid & 31;
    const int w = tid >> 5;
    const int g = lane >> 2, t4 = lane & 3;
    const int qt = blockIdx.x;
    const int bh = blockIdx.y;
    const int b = bh >> 4, h = bh & 15;
    const int q0 = qt * 64;
    const size_t hb = (size_t)bh * L_ * HD_;

    const int lrow = lane & 15;
    const int lcol8 = ((lane >> 4) << 3);

    // ---- load Q hi/lo ----
    {
        const __half* srcs[2] = {Qhg + hb, Qlg + hb};
        const uint32_t dsts[2] = {uQh, uQl};
#pragma unroll
        for (int j = 0; j < 16; j++) {
            int idx = tid + j * 128;
            int tile = idx >> 10, r = (idx >> 4) & 63, ch = idx & 15;
            cp_async16(dsts[tile] + (uint32_t)(r * AT_SW + ch * 8) * 2,
                       srcs[tile] + (size_t)(q0 + r) * 128 + ch * 8);
        }
        CP_COMMIT();
    }

    float acc_o[16][4];
#pragma unroll
    for (int j = 0; j < 16; j++)
#pragma unroll
        for (int c = 0; c < 4; c++) acc_o[j][c] = 0.f;
    float mrow[2] = {-1e30f, -1e30f};
    float lrowv[2] = {0.f, 0.f};

    const __half* ksrc[4] = {Khg + hb, Klg + hb, Vhg + hb, Vlg + hb};
    const uint32_t kdst[4] = {uKh, uKl, uVh, uVl};

    for (int kt = 0; kt <= qt; kt++) {
        const int k0 = kt * 64;
        __syncthreads();
#pragma unroll
        for (int j = 0; j < 32; j++) {
            int idx = tid + j * 128;
            int tile = idx >> 10, r = (idx >> 4) & 63, ch = idx & 15;
            cp_async16(kdst[tile] + (uint32_t)(r * AT_SW + ch * 8) * 2,
                       ksrc[tile] + (size_t)(k0 + r) * 128 + ch * 8);
        }
        CP_COMMIT();
        CP_WAIT(0);
        __syncthreads();

        // ---- S = Q K^T (hi*hi + hi*lo + lo*hi) ----
        float acc_s[8][4];
#pragma unroll
        for (int j = 0; j < 8; j++)
#pragma unroll
            for (int c = 0; c < 4; c++) acc_s[j][c] = 0.f;

#pragma unroll
        for (int ks = 0; ks < 8; ks++) {
            const uint32_t aoff = (uint32_t)((w * 16 + lrow) * AT_SW + ks * 16 + lcol8) * 2;
            uint32_t aQhf[4], aQlf[4];
            ldsm4(aQhf, uQh + aoff);
            ldsm4(aQlf, uQl + aoff);
#pragma unroll
            for (int ng = 0; ng < 4; ng++) {
                const uint32_t boff =
                    (uint32_t)((ng * 16 + lrow) * AT_SW + ks * 16 + lcol8) * 2;
                uint32_t bKhf[4], bKlf[4];
                ldsm4(bKhf, uKh + boff);
                ldsm4(bKlf, uKl + boff);
                uint32_t b0h[2] = {bKhf[0], bKhf[2]}, b1h[2] = {bKhf[1], bKhf[3]};
                uint32_t b0l[2] = {bKlf[0], bKlf[2]}, b1l[2] = {bKlf[1], bKlf[3]};
                mma16816(acc_s[2 * ng],     aQhf, b0h);
                mma16816(acc_s[2 * ng + 1], aQhf, b1h);
                mma16816(acc_s[2 * ng],     aQhf, b0l);
                mma16816(acc_s[2 * ng + 1], aQhf, b1l);
                mma16816(acc_s[2 * ng],     aQlf, b0h);
                mma16816(acc_s[2 * ng + 1], aQlf, b1h);
            }
        }

        // ---- causal mask on diagonal tile ----
        if (kt == qt) {
#pragma unroll
            for (int j = 0; j < 8; j++)
#pragma unroll
                for (int c = 0; c < 4; c++) {
                    int col = j * 8 + 2 * t4 + (c & 1);
                    int rowr = w * 16 + g + 8 * (c >> 1);
                    if (col > rowr) acc_s[j][c] = -1e30f;
                }
        }

        // ---- online softmax (rows g, g+8) ----
        uint32_t ps[8][2];
#pragma unroll
        for (int rh = 0; rh < 2; rh++) {
            float mx = -1e30f;
#pragma unroll
            for (int j = 0; j < 8; j++)
                mx = fmaxf(mx, fmaxf(acc_s[j][2 * rh], acc_s[j][2 * rh + 1]));
            mx = fmaxf(mx, __shfl_xor_sync(0xffffffffu, mx, 1));
            mx = fmaxf(mx, __shfl_xor_sync(0xffffffffu, mx, 2));
            float mnew = fmaxf(mrow[rh], mx);
            float rs = 0.f;
#pragma unroll
            for (int j = 0; j < 8; j++) {
                float p0 = __expf(acc_s[j][2 * rh]     - mnew);
                float p1 = __expf(acc_s[j][2 * rh + 1] - mnew);
                rs += p0 + p1;
                __half2 hp = __floats2half2_rn(p0, p1);
                ps[j][rh] = *(uint32_t*)&hp;
            }
            rs += __shfl_xor_sync(0xffffffffu, rs, 1);
            rs += __shfl_xor_sync(0xffffffffu, rs, 2);
            float f = __expf(mrow[rh] - mnew);
            lrowv[rh] = lrowv[rh] * f + rs;
            mrow[rh] = mnew;
#pragma unroll
            for (int j = 0; j < 16; j++) {
                acc_o[j][2 * rh]     *= f;
                acc_o[j][2 * rh + 1] *= f;
            }
        }

        // ---- O += P V (P fp16, V hi/lo) ----
#pragma unroll
        for (int kk = 0; kk < 4; kk++) {
            uint32_t a[4] = {ps[2 * kk][0], ps[2 * kk][1],
                             ps[2 * kk + 1][0], ps[2 * kk + 1][1]};
#pragma unroll
            for (int nd = 0; nd < 8; nd++) {
                const uint32_t voff =
                    (uint32_t)((kk * 16 + lrow) * AT_SW + nd * 16 + lcol8) * 2;
                uint32_t vh[4], vl[4];
                ldsm4t(vh, uVh + voff);
                ldsm4t(vl, uVl + voff);
                mma16816(acc_o[2 * nd],     a, &vh[0]);
                mma16816(acc_o[2 * nd + 1], a, &vh[2]);
                mma16816(acc_o[2 * nd],     a, &vl[0]);
                mma16816(acc_o[2 * nd + 1], a, &vl[2]);
            }
        }
    }

    // ---- epilogue: y[b, l, h*128+d] as fp16 hi/lo ----
#pragma unroll
    for (int rh = 0; rh < 2; rh++) {
        const int qi = q0 + w * 16 + g + 8 * rh;
        const float inv = 1.f / lrowv[rh];
        const size_t base = ((size_t)(b * L_ + qi)) * H_ + h * HD_;
#pragma unroll
        for (int j = 0; j < 16; j++) {
            float v0 = acc_o[j][2 * rh] * inv;
            float v1 = acc_o[j][2 * rh + 1] * inv;
            __half h0 = __float2half_rn(v0), h1 = __float2half_rn(v1);
            __half l0 = __float2half_rn(v0 - __half2float(h0));
            __half l1 = __float2half_rn(v1 - __half2float(h1));
            __half2 hv = __halves2half2(h0, h1), lv = __halves2half2(l0, l1);
            *(__half2*)&Yh[base + j * 8 + 2 * t4] = hv;
            *(__half2*)&Yl[base + j * 8 + 2 * t4] = lv;
        }
    }
}

// ================= launch ====================================================
extern "C" void kernel_launch(void* const* d_in, const int* in_sizes, int n_in,
                              void* d_out, int out_size)
{
    (void)in_sizes; (void)n_in; (void)out_size;
    const float* x    = (const float*)d_in[0];
    const float* Wqkv = (const float*)d_in[1];
    const float* bqkv = (const float*)d_in[2];
    const float* Wfc2 = (const float*)d_in[3];
    const float* bfc2 = (const float*)d_in[4];
    const float* cosb = (const float*)d_in[5];
    const float* sinb = (const float*)d_in[6];
    float* out = (float*)d_out;

    float* qkv_p;
    __half *xh, *xl, *wqh, *wql, *wfh, *wfl, *yh, *yl;
    __half *qh, *ql, *kh, *kl, *vh, *vl;
    cudaGetSymbolAddress((void**)&qkv_p, g_qkv);
    cudaGetSymbolAddress((void**)&xh, g_xh);
    cudaGetSymbolAddress((void**)&xl, g_xl);
    cudaGetSymbolAddress((void**)&wqh, g_wq_h);
    cudaGetSymbolAddress((void**)&wql, g_wq_l);
    cudaGetSymbolAddress((void**)&wfh, g_wf_h);
    cudaGetSymbolAddress((void**)&wfl, g_wf_l);
    cudaGetSymbolAddress((void**)&yh, g_yh);
    cudaGetSymbolAddress((void**)&yl, g_yl);
    cudaGetSymbolAddress((void**)&qh, g_qh);
    cudaGetSymbolAddress((void**)&ql, g_ql);
    cudaGetSymbolAddress((void**)&kh, g_kh);
    cudaGetSymbolAddress((void**)&kl, g_kl);
    cudaGetSymbolAddress((void**)&vh, g_vh);
    cudaGetSymbolAddress((void**)&vl, g_vl);

    cudaFuncSetAttribute(gemm_mma<0>,
                         cudaFuncAttributeMaxDynamicSharedMemorySize, GEMM_SMEM);
    cudaFuncSetAttribute(gemm_mma<1>,
                         cudaFuncAttributeMaxDynamicSharedMemorySize, GEMM_SMEM);
    cudaFuncSetAttribute(attn_mma,
                         cudaFuncAttributeMaxDynamicSharedMemorySize, ATT_SMEM);

    // input conversions
    split_fp16<<<(M_ * H_) / 1024, 256>>>(x, xh, xl, (M_ * H_) / 4);
    transpose_split<<<dim3(N1_ / 32, H_ / 32), dim3(32, 8)>>>(Wqkv, wqh, wql, H_, N1_);
    transpose_split<<<dim3(H_ / 32, H_ / 32), dim3(32, 8)>>>(Wfc2, wfh, wfl, H_, H_);

    // 1) qkv = x @ Wqkv + bqkv
    gemm_mma<0><<<dim3(N1_ / 128, M_ / 128), 256, GEMM_SMEM>>>(
        xh, xl, wqh, wql, bqkv, qkv_p, N1_, H_);
    // 2) RoPE + head scatter -> fp16 hi/lo
    rope_scatter<<<M_, 256>>>(cosb, sinb, qkv_p, qh, ql, kh, kl, vh, vl);
    // 3) causal flash attention (HMMA) -> yh/yl fp16
    attn_mma<<<dim3(32, 64), 128, ATT_SMEM>>>(qh, ql, kh, kl, vh, vl, yh, yl);
    // 4) out = silu(y @ Wfc2 + bfc2)
    gemm_mma<1><<<dim3(H_ / 128, M_ / 128), 256, GEMM_SMEM>>>(
        yh, yl, wfh, wfl, bfc2, out, H_, H_);
}

// round 8
// speedup vs baseline: 4.1393x; 1.4295x over previous
#include <cuda_runtime.h>
#include <cuda_fp16.h>
#include <math.h>
#include <stdint.h>

#define B_   4
#define L_   2048
#define H_   2048
#define NH_  16
#define HD_  128
#define M_   8192           // B*L
#define N1_  6144           // 3*H

// ================= scratch ===================================================
__device__ float g_qkv[(size_t)M_ * N1_];
__device__ __half g_xh[(size_t)M_ * H_];
__device__ __half g_wq_h[(size_t)N1_ * H_];   // Wqkv^T [6144][2048]
__device__ __half g_wq_l[(size_t)N1_ * H_];
__device__ __half g_wf_h[(size_t)H_ * H_];    // Wfc2^T [2048][2048]
__device__ __half g_wf_l[(size_t)H_ * H_];
__device__ __half g_yh[(size_t)M_ * H_];
__device__ __half g_qh[(size_t)M_ * H_];      // [b,h,l,d]
__device__ __half g_kh[(size_t)M_ * H_];
__device__ __half g_kl[(size_t)M_ * H_];
__device__ __half g_vh[(size_t)M_ * H_];
__device__ __half g_vl[(size_t)M_ * H_];

// ================= small helpers ============================================
__device__ __forceinline__ uint32_t smem_u32(const void* p) {
    uint32_t a;
    asm("{ .reg .u64 t; cvta.to.shared.u64 t, %1; cvt.u32.u64 %0, t; }"
        : "=r"(a) : "l"(p));
    return a;
}
__device__ __forceinline__ void ldsm4(uint32_t* r, uint32_t addr) {
    asm volatile("ldmatrix.sync.aligned.m8n8.x4.shared.b16 {%0,%1,%2,%3}, [%4];"
        : "=r"(r[0]), "=r"(r[1]), "=r"(r[2]), "=r"(r[3]) : "r"(addr));
}
__device__ __forceinline__ void ldsm4t(uint32_t* r, uint32_t addr) {
    asm volatile("ldmatrix.sync.aligned.m8n8.x4.trans.shared.b16 {%0,%1,%2,%3}, [%4];"
        : "=r"(r[0]), "=r"(r[1]), "=r"(r[2]), "=r"(r[3]) : "r"(addr));
}
__device__ __forceinline__ void mma16816(float* c, const uint32_t* a, const uint32_t* b) {
    asm volatile("mma.sync.aligned.m16n8k16.row.col.f32.f16.f16.f32 "
        "{%0,%1,%2,%3}, {%4,%5,%6,%7}, {%8,%9}, {%0,%1,%2,%3};"
        : "+f"(c[0]), "+f"(c[1]), "+f"(c[2]), "+f"(c[3])
        : "r"(a[0]), "r"(a[1]), "r"(a[2]), "r"(a[3]), "r"(b[0]), "r"(b[1]));
}
__device__ __forceinline__ void cp_async16(uint32_t saddr, const void* gaddr) {
    asm volatile("cp.async.cg.shared.global [%0], [%1], 16;"
                 :: "r"(saddr), "l"(gaddr));
}
#define CP_COMMIT() asm volatile("cp.async.commit_group;")
#define CP_WAIT(N)  asm volatile("cp.async.wait_group %0;" :: "n"(N))

// ================= conversion kernels =======================================
// fp32 -> fp16 (hi only)
__global__ __launch_bounds__(256) void cvt_fp16(
    const float* __restrict__ X, __half* __restrict__ Xh, int n4)
{
    int i = blockIdx.x * 256 + threadIdx.x;
    if (i >= n4) return;
    float4 v = *(const float4*)(X + (size_t)i * 4);
    __half2 a = __floats2half2_rn(v.x, v.y);
    __half2 b = __floats2half2_rn(v.z, v.w);
    uint2 o = make_uint2(*(uint32_t*)&a, *(uint32_t*)&b);
    *(uint2*)(Xh + (size_t)i * 4) = o;
}

// W [K x N] fp32 -> Wt hi/lo [N x K] fp16
__global__ __launch_bounds__(256) void transpose_split(
    const float* __restrict__ W, __half* __restrict__ Th, __half* __restrict__ Tl,
    int K, int N)
{
    __shared__ float t[32][33];
    int n0 = blockIdx.x * 32, k0 = blockIdx.y * 32;
    int tx = threadIdx.x, ty = threadIdx.y;
#pragma unroll
    for (int i = ty; i < 32; i += 8)
        t[i][tx] = W[(size_t)(k0 + i) * N + n0 + tx];
    __syncthreads();
#pragma unroll
    for (int i = ty; i < 32; i += 8) {
        float v = t[tx][i];
        __half h = __float2half_rn(v);
        Th[(size_t)(n0 + i) * K + k0 + tx] = h;
        Tl[(size_t)(n0 + i) * K + k0 + tx] = __float2half_rn(v - __half2float(h));
    }
}

// ================= 2-pass split-fp16 warp-MMA GEMM ==========================
// C = Ah @ (Bh + Bl)^T + bias: activation fp16, weight hi/lo.
// Block 128x128, K-step 32, 8 warps (warp 64x32), 3-stage cp.async.
#define GT_ROWSTRIDE 80
#define GT_TILE_B    (128 * GT_ROWSTRIDE)     // 10240 B
#define GT_STAGE_B   (3 * GT_TILE_B)          // A, Bh, Bl  = 30720 B
#define GEMM_SMEM    (3 * GT_STAGE_B)         // 92160 B

template<int SILU>
__global__ __launch_bounds__(256, 2) void gemm_mma(
    const __half* __restrict__ Ah,
    const __half* __restrict__ Bh, const __half* __restrict__ Bl,
    const float* __restrict__ bias, float* __restrict__ C,
    int Ng, int Kg)
{
    extern __shared__ char smem[];
    const uint32_t sb = smem_u32(smem);
    const int tid  = threadIdx.x;
    const int lane = tid & 31;
    const int wid  = tid >> 5;
    const int wm   = wid & 1;
    const int wn   = wid >> 1;
    const int m0 = blockIdx.y * 128;
    const int n0 = blockIdx.x * 128;

    const __half* gsrc[3] = { Ah + (size_t)m0 * Kg,
                              Bh + (size_t)n0 * Kg, Bl + (size_t)n0 * Kg };

    const int a_row = ((lane >> 3) & 1) * 8 + (lane & 7);
    const int a_kof = (lane >> 4) * 8;
    const int b_row = (lane >> 4) * 8 + (lane & 7);
    const int b_kof = ((lane >> 3) & 1) * 8;

    float acc[4][4][4];
#pragma unroll
    for (int i = 0; i < 4; i++)
#pragma unroll
        for (int j = 0; j < 4; j++)
#pragma unroll
            for (int k = 0; k < 4; k++) acc[i][j][k] = 0.f;

    const int nst = Kg >> 5;

    auto load_stage = [&](int s) {
        const uint32_t stb = sb + (s % 3) * GT_STAGE_B;
        const int k0 = s << 5;
#pragma unroll
        for (int j = 0; j < 6; j++) {
            int c = tid + j * 256;          // 0..1535
            int tile = c >> 9;              // 0..2
            int idx = c & 511;
            int r = idx >> 2, q = idx & 3;
            uint32_t sa = stb + tile * GT_TILE_B + r * GT_ROWSTRIDE + q * 16;
            cp_async16(sa, gsrc[tile] + (size_t)r * Kg + k0 + q * 8);
        }
        CP_COMMIT();
    };

    load_stage(0);
    load_stage(1);

    for (int i = 0; i < nst; i++) {
        CP_WAIT(1);
        __syncthreads();
        if (i + 2 < nst) load_stage(i + 2);

        const uint32_t stb = sb + (i % 3) * GT_STAGE_B;
        const uint32_t sA  = stb;
        const uint32_t sBh = stb + GT_TILE_B;
        const uint32_t sBl = stb + 2 * GT_TILE_B;

#pragma unroll
        for (int kk = 0; kk < 2; kk++) {
            const int kb = kk * 16;
            uint32_t ah[4][4], bh[2][4], bl[2][4];
#pragma unroll
            for (int mi = 0; mi < 4; mi++) {
                uint32_t ro = (uint32_t)((wm * 64 + mi * 16 + a_row) * GT_ROWSTRIDE
                                         + (kb + a_kof) * 2);
                ldsm4(ah[mi], sA + ro);
            }
#pragma unroll
            for (int nj = 0; nj < 2; nj++) {
                uint32_t ro = (uint32_t)((wn * 32 + nj * 16 + b_row) * GT_ROWSTRIDE
                                         + (kb + b_kof) * 2);
                ldsm4(bh[nj], sBh + ro);
                ldsm4(bl[nj], sBl + ro);
            }
#pragma unroll
            for (int mi = 0; mi < 4; mi++)
#pragma unroll
                for (int ni = 0; ni < 4; ni++) {
                    const uint32_t* bhf = &bh[ni >> 1][2 * (ni & 1)];
                    const uint32_t* blf = &bl[ni >> 1][2 * (ni & 1)];
                    mma16816(acc[mi][ni], ah[mi], bhf);
                    mma16816(acc[mi][ni], ah[mi], blf);
                }
        }
        __syncthreads();
    }

    const int g = lane >> 2, t4 = lane & 3;
#pragma unroll
    for (int mi = 0; mi < 4; mi++) {
#pragma unroll
        for (int ni = 0; ni < 4; ni++) {
            int row0 = m0 + wm * 64 + mi * 16 + g;
            int col  = n0 + wn * 32 + ni * 8 + t4 * 2;
            float b0 = bias[col], b1 = bias[col + 1];
            float z0 = acc[mi][ni][0] + b0, z1 = acc[mi][ni][1] + b1;
            float z2 = acc[mi][ni][2] + b0, z3 = acc[mi][ni][3] + b1;
            if (SILU) {
                z0 = z0 / (1.f + expf(-z0)); z1 = z1 / (1.f + expf(-z1));
                z2 = z2 / (1.f + expf(-z2)); z3 = z3 / (1.f + expf(-z3));
            }
            *(float2*)&C[(size_t)row0 * Ng + col]       = make_float2(z0, z1);
            *(float2*)&C[(size_t)(row0 + 8) * Ng + col] = make_float2(z2, z3);
        }
    }
}

// ================= RoPE + head-scatter ======================================
__global__ __launch_bounds__(256) void rope_scatter(
    const float* __restrict__ cosb, const float* __restrict__ sinb,
    const float* __restrict__ qkv,
    __half* __restrict__ Qh,
    __half* __restrict__ Kh, __half* __restrict__ Kl,
    __half* __restrict__ Vh, __half* __restrict__ Vl)
{
    __shared__ float row[6144];
    __shared__ float cr[1024];
    __shared__ float sr[1024];

    const int m = blockIdx.x;
    const int b = m >> 11;
    const int l = m & 2047;
    const float* src = qkv + (size_t)m * 6144;

    for (int i = threadIdx.x; i < 1536; i += 256)
        *(float4*)&row[i * 4] = *(const float4*)&src[i * 4];
    {
        int i4 = threadIdx.x;
        *(float4*)&cr[i4 * 4] = *(const float4*)&cosb[(size_t)l * 1024 + i4 * 4];
        *(float4*)&sr[i4 * 4] = *(const float4*)&sinb[(size_t)l * 1024 + i4 * 4];
    }
    __syncthreads();

    const float scale = 0.08838834764831845f;
#pragma unroll
    for (int it = 0; it < 4; it++) {
        int u = it * 256 + threadIdx.x;
        int h = u >> 6;
        int dlo = u & 63;
        int jj = dlo * 16 + h;
        float c = cr[jj], s = sr[jj];
        float q1 = row[jj],        q2 = row[jj + 1024];
        float k1 = row[2048 + jj], k2 = row[3072 + jj];
        size_t base = (((size_t)b * 16 + h) * 2048 + l) * 128;

        // Q: fp16 hi only
        Qh[base + dlo]      = __float2half_rn(( q1 * c + q2 * s) * scale);
        Qh[base + dlo + 64] = __float2half_rn((-q1 * s + q2 * c) * scale);
        // K, V: hi/lo
        float kv0 =  k1 * c + k2 * s;
        float kv1 = -k1 * s + k2 * c;
        float vv0 = row[4096 + jj];
        float vv1 = row[4096 + jj + 1024];
        __half h0 = __float2half_rn(kv0);
        __half h1 = __float2half_rn(kv1);
        Kh[base + dlo]      = h0;
        Kh[base + dlo + 64] = h1;
        Kl[base + dlo]      = __float2half_rn(kv0 - __half2float(h0));
        Kl[base + dlo + 64] = __float2half_rn(kv1 - __half2float(h1));
        __half v0 = __float2half_rn(vv0);
        __half v1 = __float2half_rn(vv1);
        Vh[base + dlo]      = v0;
        Vh[base + dlo + 64] = v1;
        Vl[base + dlo]      = __float2half_rn(vv0 - __half2float(v0));
        Vl[base + dlo + 64] = __float2half_rn(vv1 - __half2float(v1));
    }
}

// ================= causal flash attention (HMMA) ============================
// Block: 64 q-rows, 4 warps. Tiles: Qh, Kh, Kl, Vh, Vl (5 x 64x128 padded)
#define AT_SW 136
#define AT_TILE_H (64 * AT_SW)
#define ATT_SMEM (5 * AT_TILE_H * 2)            // 87040 B

__global__ __launch_bounds__(128) void attn_mma(
    const __half* __restrict__ Qhg,
    const __half* __restrict__ Khg, const __half* __restrict__ Klg,
    const __half* __restrict__ Vhg, const __half* __restrict__ Vlg,
    __half* __restrict__ Yh)
{
    extern __shared__ __half smh[];
    __half* sQh = smh;
    __half* sKh = sQh + AT_TILE_H;
    __half* sKl = sKh + AT_TILE_H;
    __half* sVh = sKl + AT_TILE_H;
    __half* sVl = sVh + AT_TILE_H;

    const uint32_t uQh = smem_u32(sQh);
    const uint32_t uKh = smem_u32(sKh), uKl = smem_u32(sKl);
    const uint32_t uVh = smem_u32(sVh), uVl = smem_u32(sVl);

    const int tid = threadIdx.x;
    const int lane = tid & 31;
    const int w = tid >> 5;
    const int g = lane >> 2, t4 = lane & 3;
    const int qt = blockIdx.x;
    const int bh = blockIdx.y;
    const int b = bh >> 4, h = bh & 15;
    const int q0 = qt * 64;
    const size_t hb = (size_t)bh * L_ * HD_;

    const int lrow = lane & 15;
    const int lcol8 = ((lane >> 4) << 3);

    // ---- load Q (1 tile, 1024 chunks) ----
    {
#pragma unroll
        for (int j = 0; j < 8; j++) {
            int idx = tid + j * 128;
            int r = idx >> 4, ch = idx & 15;
            cp_async16(uQh + (uint32_t)(r * AT_SW + ch * 8) * 2,
                       Qhg + hb + (size_t)(q0 + r) * 128 + ch * 8);
        }
        CP_COMMIT();
    }

    float acc_o[16][4];
#pragma unroll
    for (int j = 0; j < 16; j++)
#pragma unroll
        for (int c = 0; c < 4; c++) acc_o[j][c] = 0.f;
    float mrow[2] = {-1e30f, -1e30f};
    float lrowv[2] = {0.f, 0.f};

    const __half* ksrc[4] = {Khg + hb, Klg + hb, Vhg + hb, Vlg + hb};
    const uint32_t kdst[4] = {uKh, uKl, uVh, uVl};

    for (int kt = 0; kt <= qt; kt++) {
        const int k0 = kt * 64;
        __syncthreads();
#pragma unroll
        for (int j = 0; j < 32; j++) {
            int idx = tid + j * 128;
            int tile = idx >> 10, r = (idx >> 4) & 63, ch = idx & 15;
            cp_async16(kdst[tile] + (uint32_t)(r * AT_SW + ch * 8) * 2,
                       ksrc[tile] + (size_t)(k0 + r) * 128 + ch * 8);
        }
        CP_COMMIT();
        CP_WAIT(0);
        __syncthreads();

        // ---- S = Q K^T (Qh*Kh + Qh*Kl) ----
        float acc_s[8][4];
#pragma unroll
        for (int j = 0; j < 8; j++)
#pragma unroll
            for (int c = 0; c < 4; c++) acc_s[j][c] = 0.f;

#pragma unroll
        for (int ks = 0; ks < 8; ks++) {
            const uint32_t aoff = (uint32_t)((w * 16 + lrow) * AT_SW + ks * 16 + lcol8) * 2;
            uint32_t aQ[4];
            ldsm4(aQ, uQh + aoff);
#pragma unroll
            for (int ng = 0; ng < 4; ng++) {
                const uint32_t boff =
                    (uint32_t)((ng * 16 + lrow) * AT_SW + ks * 16 + lcol8) * 2;
                uint32_t bKhf[4], bKlf[4];
                ldsm4(bKhf, uKh + boff);
                ldsm4(bKlf, uKl + boff);
                uint32_t b0h[2] = {bKhf[0], bKhf[2]}, b1h[2] = {bKhf[1], bKhf[3]};
                uint32_t b0l[2] = {bKlf[0], bKlf[2]}, b1l[2] = {bKlf[1], bKlf[3]};
                mma16816(acc_s[2 * ng],     aQ, b0h);
                mma16816(acc_s[2 * ng + 1], aQ, b1h);
                mma16816(acc_s[2 * ng],     aQ, b0l);
                mma16816(acc_s[2 * ng + 1], aQ, b1l);
            }
        }

        // ---- causal mask on diagonal tile ----
        if (kt == qt) {
#pragma unroll
            for (int j = 0; j < 8; j++)
#pragma unroll
                for (int c = 0; c < 4; c++) {
                    int col = j * 8 + 2 * t4 + (c & 1);
                    int rowr = w * 16 + g + 8 * (c >> 1);
                    if (col > rowr) acc_s[j][c] = -1e30f;
                }
        }

        // ---- online softmax (rows g, g+8) ----
        uint32_t ps[8][2];
#pragma unroll
        for (int rh = 0; rh < 2; rh++) {
            float mx = -1e30f;
#pragma unroll
            for (int j = 0; j < 8; j++)
                mx = fmaxf(mx, fmaxf(acc_s[j][2 * rh], acc_s[j][2 * rh + 1]));
            mx = fmaxf(mx, __shfl_xor_sync(0xffffffffu, mx, 1));
            mx = fmaxf(mx, __shfl_xor_sync(0xffffffffu, mx, 2));
            float mnew = fmaxf(mrow[rh], mx);
            float rs = 0.f;
#pragma unroll
            for (int j = 0; j < 8; j++) {
                float p0 = __expf(acc_s[j][2 * rh]     - mnew);
                float p1 = __expf(acc_s[j][2 * rh + 1] - mnew);
                rs += p0 + p1;
                __half2 hp = __floats2half2_rn(p0, p1);
                ps[j][rh] = *(uint32_t*)&hp;
            }
            rs += __shfl_xor_sync(0xffffffffu, rs, 1);
            rs += __shfl_xor_sync(0xffffffffu, rs, 2);
            float f = __expf(mrow[rh] - mnew);
            lrowv[rh] = lrowv[rh] * f + rs;
            mrow[rh] = mnew;
#pragma unroll
            for (int j = 0; j < 16; j++) {
                acc_o[j][2 * rh]     *= f;
                acc_o[j][2 * rh + 1] *= f;
            }
        }

        // ---- O += P V (P fp16, V hi/lo) ----
#pragma unroll
        for (int kk = 0; kk < 4; kk++) {
            uint32_t a[4] = {ps[2 * kk][0], ps[2 * kk][1],
                             ps[2 * kk + 1][0], ps[2 * kk + 1][1]};
#pragma unroll
            for (int nd = 0; nd < 8; nd++) {
                const uint32_t voff =
                    (uint32_t)((kk * 16 + lrow) * AT_SW + nd * 16 + lcol8) * 2;
                uint32_t vh[4], vl[4];
                ldsm4t(vh, uVh + voff);
                ldsm4t(vl, uVl + voff);
                mma16816(acc_o[2 * nd],     a, &vh[0]);
                mma16816(acc_o[2 * nd + 1], a, &vh[2]);
                mma16816(acc_o[2 * nd],     a, &vl[0]);
                mma16816(acc_o[2 * nd + 1], a, &vl[2]);
            }
        }
    }

    // ---- epilogue: y[b, l, h*128+d] fp16 ----
#pragma unroll
    for (int rh = 0; rh < 2; rh++) {
        const int qi = q0 + w * 16 + g + 8 * rh;
        const float inv = 1.f / lrowv[rh];
        const size_t base = ((size_t)(b * L_ + qi)) * H_ + h * HD_;
#pragma unroll
        for (int j = 0; j < 16; j++) {
            __half2 hv = __floats2half2_rn(acc_o[j][2 * rh] * inv,
                                           acc_o[j][2 * rh + 1] * inv);
            *(__half2*)&Yh[base + j * 8 + 2 * t4] = hv;
        }
    }
}

// ================= launch ====================================================
extern "C" void kernel_launch(void* const* d_in, const int* in_sizes, int n_in,
                              void* d_out, int out_size)
{
    (void)in_sizes; (void)n_in; (void)out_size;
    const float* x    = (const float*)d_in[0];
    const float* Wqkv = (const float*)d_in[1];
    const float* bqkv = (const float*)d_in[2];
    const float* Wfc2 = (const float*)d_in[3];
    const float* bfc2 = (const float*)d_in[4];
    const float* cosb = (const float*)d_in[5];
    const float* sinb = (const float*)d_in[6];
    float* out = (float*)d_out;

    float* qkv_p;
    __half *xh, *wqh, *wql, *wfh, *wfl, *yh;
    __half *qh, *kh, *kl, *vh, *vl;
    cudaGetSymbolAddress((void**)&qkv_p, g_qkv);
    cudaGetSymbolAddress((void**)&xh, g_xh);
    cudaGetSymbolAddress((void**)&wqh, g_wq_h);
    cudaGetSymbolAddress((void**)&wql, g_wq_l);
    cudaGetSymbolAddress((void**)&wfh, g_wf_h);
    cudaGetSymbolAddress((void**)&wfl, g_wf_l);
    cudaGetSymbolAddress((void**)&yh, g_yh);
    cudaGetSymbolAddress((void**)&qh, g_qh);
    cudaGetSymbolAddress((void**)&kh, g_kh);
    cudaGetSymbolAddress((void**)&kl, g_kl);
    cudaGetSymbolAddress((void**)&vh, g_vh);
    cudaGetSymbolAddress((void**)&vl, g_vl);

    cudaFuncSetAttribute(gemm_mma<0>,
                         cudaFuncAttributeMaxDynamicSharedMemorySize, GEMM_SMEM);
    cudaFuncSetAttribute(gemm_mma<1>,
                         cudaFuncAttributeMaxDynamicSharedMemorySize, GEMM_SMEM);
    cudaFuncSetAttribute(attn_mma,
                         cudaFuncAttributeMaxDynamicSharedMemorySize, ATT_SMEM);

    // input conversions
    cvt_fp16<<<(M_ * H_) / 1024, 256>>>(x, xh, (M_ * H_) / 4);
    transpose_split<<<dim3(N1_ / 32, H_ / 32), dim3(32, 8)>>>(Wqkv, wqh, wql, H_, N1_);
    transpose_split<<<dim3(H_ / 32, H_ / 32), dim3(32, 8)>>>(Wfc2, wfh, wfl, H_, H_);

    // 1) qkv = x @ Wqkv + bqkv
    gemm_mma<0><<<dim3(N1_ / 128, M_ / 128), 256, GEMM_SMEM>>>(
        xh, wqh, wql, bqkv, qkv_p, N1_, H_);
    // 2) RoPE + head scatter
    rope_scatter<<<M_, 256>>>(cosb, sinb, qkv_p, qh, kh, kl, vh, vl);
    // 3) causal flash attention -> yh fp16
    attn_mma<<<dim3(32, 64), 128, ATT_SMEM>>>(qh, kh, kl, vh, vl, yh);
    // 4) out = silu(y @ Wfc2 + bfc2)
    gemm_mma<1><<<dim3(H_ / 128, M_ / 128), 256, GEMM_SMEM>>>(
        yh, wfh, wfl, bfc2, out, H_, H_);
}